// round 10
// baseline (speedup 1.0000x reference)
#include <cuda_runtime.h>
#include <math.h>
#include <stdint.h>

// Problem constants
#define BATCH   8
#define SEQ     2048
#define HID     1024
#define NPB     (SEQ * HID)        // 2,097,152 elements per batch
#define VEC_PB  (NPB / 4)          // 524,288 float4 per batch
#define TOTALV  (BATCH * VEC_PB)   // 4,194,304 float4 total
#define RANK0   1048576u           // 0-indexed ascending rank of threshold (N - k)
#define HBLK    128                // hist blocks per batch (16 rows each)
#define FBLK    256                // final blocks per batch (8 rows each)

// Static scratch (no runtime allocation allowed)
__device__ __align__(16) float    g_imp5[5 * HID];       // sigmoid(band)*sigmoid(dim)
__device__ unsigned               g_hist[2][BATCH][2048];
__device__ unsigned               g_d0[BATCH];           // selected digit, pass 0
__device__ unsigned               g_r1[BATCH];           // remaining rank after pass 0
__device__ float                  g_thr[BATCH];
__device__ unsigned               g_done0, g_done1;      // last-block-done counters

__device__ __forceinline__ float sigmoidf_fast(float x) {
    return 1.0f / (1.0f + __expf(-x));
}

// band(t): 0 for t<128, else floor(log2(t>>7)) + 1   (T=2048, L=4)
__device__ __forceinline__ int band_of(int t) {
    return (t >= 128) ? (32 - __clz(t >> 7)) : 0;
}

// ---------------------------------------------------------------------------
// setup: zero histograms + done counters, build importance table
// ---------------------------------------------------------------------------
__global__ void setup_kernel(const float* __restrict__ bi, const float* __restrict__ di) {
    int i = blockIdx.x * blockDim.x + threadIdx.x;
    if (i < 2 * BATCH * 2048) ((unsigned*)g_hist)[i] = 0;
    if (i == 0) { g_done0 = 0; g_done1 = 0; }
    if (i < 5 * HID) {
        float sb = sigmoidf_fast(bi[i]);
        float sd = sigmoidf_fast(di[i & (HID - 1)]);
        g_imp5[i] = sb * sd;
    }
}

// ---------------------------------------------------------------------------
// warp-collective digit select over a 32*PER-bin histogram.
// Uses __ldcg: the histogram was produced by other blocks' global atomics,
// so bypass L1 and read L2-current values.
// ---------------------------------------------------------------------------
template <int PER>
__device__ __forceinline__ unsigned warp_select(const unsigned* __restrict__ h,
                                                unsigned rank, unsigned* rem) {
    const int lane = threadIdx.x & 31;
    unsigned s = 0;
    #pragma unroll
    for (int j = 0; j < PER; j++) s += __ldcg(&h[lane * PER + j]);

    unsigned v = s;
    #pragma unroll
    for (int o = 1; o < 32; o <<= 1) {
        unsigned t = __shfl_up_sync(0xFFFFFFFFu, v, o);
        if (lane >= o) v += t;
    }
    unsigned excl = v - s;

    bool in = (rank >= excl) && (rank < excl + s);
    unsigned m = __ballot_sync(0xFFFFFFFFu, in);
    int L = __ffs(m) - 1;

    unsigned dig = 0, r2 = 0;
    if (lane == L) {
        unsigned cum = excl;
        #pragma unroll 1
        for (int j = 0; j < PER; j++) {
            unsigned c = __ldcg(&h[lane * PER + j]);
            if (rank < cum + c) { dig = (unsigned)(lane * PER + j); r2 = rank - cum; break; }
            cum += c;
        }
    }
    dig = __shfl_sync(0xFFFFFFFFu, dig, L);
    r2  = __shfl_sync(0xFFFFFFFFu, r2,  L);
    *rem = r2;
    return dig;
}

// ---------------------------------------------------------------------------
// pass 0: histogram bits[31:21]. grid (HBLK, BATCH) x 256.
// Block = 16 contiguous rows (single band); thread = one float4 column;
// imp4 per-thread constant. Lane-interleaved 4-replica hist: lanes hitting
// the same hot bin land on 4 adjacent words -> conflict degree /4.
// Last block to finish performs select0 inline (saves a launch).
// ---------------------------------------------------------------------------
__global__ void __launch_bounds__(256) hist0_kernel(const float4* __restrict__ coeffs) {
    __shared__ unsigned sh[4 * 2048];
    __shared__ bool s_last;
    const int tid = threadIdx.x;
    const unsigned rep = tid & 3;

    for (int i = tid; i < 4 * 2048; i += 256) sh[i] = 0;
    __syncthreads();

    const int batch = blockIdx.y;
    const int band = band_of(blockIdx.x << 4);
    const float4 imp = *reinterpret_cast<const float4*>(&g_imp5[band * HID + (tid << 2)]);
    const float4* p = coeffs + (size_t)batch * VEC_PB + (size_t)blockIdx.x * (16 * 256) + tid;

    #pragma unroll
    for (int r = 0; r < 16; r += 4) {
        float4 c0 = __ldg(p + (r + 0) * 256);
        float4 c1 = __ldg(p + (r + 1) * 256);
        float4 c2 = __ldg(p + (r + 2) * 256);
        float4 c3 = __ldg(p + (r + 3) * 256);
        atomicAdd(&sh[((__float_as_uint(imp.x * fabsf(c0.x)) >> 21) << 2) | rep], 1u);
        atomicAdd(&sh[((__float_as_uint(imp.y * fabsf(c0.y)) >> 21) << 2) | rep], 1u);
        atomicAdd(&sh[((__float_as_uint(imp.z * fabsf(c0.z)) >> 21) << 2) | rep], 1u);
        atomicAdd(&sh[((__float_as_uint(imp.w * fabsf(c0.w)) >> 21) << 2) | rep], 1u);
        atomicAdd(&sh[((__float_as_uint(imp.x * fabsf(c1.x)) >> 21) << 2) | rep], 1u);
        atomicAdd(&sh[((__float_as_uint(imp.y * fabsf(c1.y)) >> 21) << 2) | rep], 1u);
        atomicAdd(&sh[((__float_as_uint(imp.z * fabsf(c1.z)) >> 21) << 2) | rep], 1u);
        atomicAdd(&sh[((__float_as_uint(imp.w * fabsf(c1.w)) >> 21) << 2) | rep], 1u);
        atomicAdd(&sh[((__float_as_uint(imp.x * fabsf(c2.x)) >> 21) << 2) | rep], 1u);
        atomicAdd(&sh[((__float_as_uint(imp.y * fabsf(c2.y)) >> 21) << 2) | rep], 1u);
        atomicAdd(&sh[((__float_as_uint(imp.z * fabsf(c2.z)) >> 21) << 2) | rep], 1u);
        atomicAdd(&sh[((__float_as_uint(imp.w * fabsf(c2.w)) >> 21) << 2) | rep], 1u);
        atomicAdd(&sh[((__float_as_uint(imp.x * fabsf(c3.x)) >> 21) << 2) | rep], 1u);
        atomicAdd(&sh[((__float_as_uint(imp.y * fabsf(c3.y)) >> 21) << 2) | rep], 1u);
        atomicAdd(&sh[((__float_as_uint(imp.z * fabsf(c3.z)) >> 21) << 2) | rep], 1u);
        atomicAdd(&sh[((__float_as_uint(imp.w * fabsf(c3.w)) >> 21) << 2) | rep], 1u);
    }
    __syncthreads();

    for (int i = tid; i < 2048; i += 256) {
        unsigned s = sh[4 * i] + sh[4 * i + 1] + sh[4 * i + 2] + sh[4 * i + 3];
        if (s) atomicAdd(&g_hist[0][batch][i], s);
    }

    // last-block-done: the final block performs select0 for all batches
    __threadfence();
    if (tid == 0) {
        unsigned done = atomicAdd(&g_done0, 1u);
        s_last = (done == HBLK * BATCH - 1);
    }
    __syncthreads();
    if (s_last) {
        __threadfence();
        const int b = tid >> 5;
        if (b < BATCH) {
            unsigned r1;
            unsigned d0 = warp_select<64>(g_hist[0][b], RANK0, &r1);
            if ((tid & 31) == 0) { g_d0[b] = d0; g_r1[b] = r1; }
        }
    }
}

// ---------------------------------------------------------------------------
// pass 1: histogram bits[20:10] among values with bits[31:21] == d0.
// Sparse updates -> 2 warp-replicas. Last block performs select1 inline.
// ---------------------------------------------------------------------------
__global__ void __launch_bounds__(256) hist1_kernel(const float4* __restrict__ coeffs) {
    __shared__ unsigned sh[2][2048];
    __shared__ bool s_last;
    const int tid = threadIdx.x;

    for (int i = tid; i < 2 * 2048; i += 256) ((unsigned*)sh)[i] = 0;
    __syncthreads();

    const int batch = blockIdx.y;
    const unsigned pref = __ldcg(&g_d0[batch]);
    unsigned* h = sh[(tid >> 5) & 1];
    const int band = band_of(blockIdx.x << 4);
    const float4 imp = *reinterpret_cast<const float4*>(&g_imp5[band * HID + (tid << 2)]);
    const float4* p = coeffs + (size_t)batch * VEC_PB + (size_t)blockIdx.x * (16 * 256) + tid;

    #pragma unroll
    for (int r = 0; r < 16; r += 4) {
        float4 c0 = __ldg(p + (r + 0) * 256);
        float4 c1 = __ldg(p + (r + 1) * 256);
        float4 c2 = __ldg(p + (r + 2) * 256);
        float4 c3 = __ldg(p + (r + 3) * 256);
        unsigned bb[16];
        bb[0]  = __float_as_uint(imp.x * fabsf(c0.x));
        bb[1]  = __float_as_uint(imp.y * fabsf(c0.y));
        bb[2]  = __float_as_uint(imp.z * fabsf(c0.z));
        bb[3]  = __float_as_uint(imp.w * fabsf(c0.w));
        bb[4]  = __float_as_uint(imp.x * fabsf(c1.x));
        bb[5]  = __float_as_uint(imp.y * fabsf(c1.y));
        bb[6]  = __float_as_uint(imp.z * fabsf(c1.z));
        bb[7]  = __float_as_uint(imp.w * fabsf(c1.w));
        bb[8]  = __float_as_uint(imp.x * fabsf(c2.x));
        bb[9]  = __float_as_uint(imp.y * fabsf(c2.y));
        bb[10] = __float_as_uint(imp.z * fabsf(c2.z));
        bb[11] = __float_as_uint(imp.w * fabsf(c2.w));
        bb[12] = __float_as_uint(imp.x * fabsf(c3.x));
        bb[13] = __float_as_uint(imp.y * fabsf(c3.y));
        bb[14] = __float_as_uint(imp.z * fabsf(c3.z));
        bb[15] = __float_as_uint(imp.w * fabsf(c3.w));
        #pragma unroll
        for (int j = 0; j < 16; j++)
            if ((bb[j] >> 21) == pref) atomicAdd(&h[(bb[j] >> 10) & 2047], 1u);
    }
    __syncthreads();

    for (int i = tid; i < 2048; i += 256) {
        unsigned s = sh[0][i] + sh[1][i];
        if (s) atomicAdd(&g_hist[1][batch][i], s);
    }

    // last-block-done: select1 -> threshold (midpoint of 1024-ulp bin;
    // threshold rel err <= 2^-14, measured end-to-end rel_err 3.2e-6)
    __threadfence();
    if (tid == 0) {
        unsigned done = atomicAdd(&g_done1, 1u);
        s_last = (done == HBLK * BATCH - 1);
    }
    __syncthreads();
    if (s_last) {
        __threadfence();
        const int b = tid >> 5;
        if (b < BATCH) {
            unsigned r2;
            unsigned d1 = warp_select<64>(g_hist[1][b], __ldcg(&g_r1[b]), &r2);
            if ((tid & 31) == 0)
                g_thr[b] = __uint_as_float((__ldcg(&g_d0[b]) << 21) | (d1 << 10) | 512u);
        }
    }
}

// ---------------------------------------------------------------------------
// final: out[0..V)=coeffs*mask, out[V..2V)=mask, out[2V..3V)=importance.
// grid (FBLK, BATCH) x 256: 8 rows/block for deeper wave overlap (write-bound,
// issue was 25%). imp4 per-thread constant, importance written from registers.
// ---------------------------------------------------------------------------
__global__ void __launch_bounds__(256) final_kernel(const float4* __restrict__ coeffs,
                                                    const float* __restrict__ temp,
                                                    float4* __restrict__ out) {
    const int tid = threadIdx.x;
    const int batch = blockIdx.y;
    const int band = band_of(blockIdx.x << 3);   // 8 rows/block; boundaries at mult of 8
    const float4 imp = *reinterpret_cast<const float4*>(&g_imp5[band * HID + (tid << 2)]);
    const float thr = __ldcg(&g_thr[batch]);
    const float inv_t = __frcp_rn(fabsf(__ldg(&temp[0])));

    const size_t vbase = (size_t)batch * VEC_PB + (size_t)blockIdx.x * (8 * 256) + tid;
    const float4* p = coeffs + vbase;

    #pragma unroll
    for (int r = 0; r < 8; r += 2) {
        float4 c0 = __ldg(p + (r + 0) * 256);
        float4 c1 = __ldg(p + (r + 1) * 256);

        float4 mk0, fl0, mk1, fl1;
        { float ci = imp.x * fabsf(c0.x); mk0.x = sigmoidf_fast((ci - thr) * inv_t); fl0.x = c0.x * mk0.x; }
        { float ci = imp.y * fabsf(c0.y); mk0.y = sigmoidf_fast((ci - thr) * inv_t); fl0.y = c0.y * mk0.y; }
        { float ci = imp.z * fabsf(c0.z); mk0.z = sigmoidf_fast((ci - thr) * inv_t); fl0.z = c0.z * mk0.z; }
        { float ci = imp.w * fabsf(c0.w); mk0.w = sigmoidf_fast((ci - thr) * inv_t); fl0.w = c0.w * mk0.w; }
        { float ci = imp.x * fabsf(c1.x); mk1.x = sigmoidf_fast((ci - thr) * inv_t); fl1.x = c1.x * mk1.x; }
        { float ci = imp.y * fabsf(c1.y); mk1.y = sigmoidf_fast((ci - thr) * inv_t); fl1.y = c1.y * mk1.y; }
        { float ci = imp.z * fabsf(c1.z); mk1.z = sigmoidf_fast((ci - thr) * inv_t); fl1.z = c1.z * mk1.z; }
        { float ci = imp.w * fabsf(c1.w); mk1.w = sigmoidf_fast((ci - thr) * inv_t); fl1.w = c1.w * mk1.w; }

        size_t ve0 = vbase + (size_t)(r + 0) * 256;
        size_t ve1 = vbase + (size_t)(r + 1) * 256;
        __stcs(&out[ve0], fl0);
        __stcs(&out[ve1], fl1);
        __stcs(&out[TOTALV + ve0], mk0);
        __stcs(&out[TOTALV + ve1], mk1);
        __stcs(&out[2 * TOTALV + ve0], imp);
        __stcs(&out[2 * TOTALV + ve1], imp);
    }
}

// ---------------------------------------------------------------------------
// launch
// ---------------------------------------------------------------------------
extern "C" void kernel_launch(void* const* d_in, const int* in_sizes, int n_in,
                              void* d_out, int out_size) {
    const float* coeffs = (const float*)d_in[0];
    const float* bi     = (const float*)d_in[1];
    const float* di     = (const float*)d_in[2];
    const float* temp   = (const float*)d_in[3];
    float* out = (float*)d_out;

    setup_kernel<<<(2 * BATCH * 2048 + 255) / 256, 256>>>(bi, di);

    dim3 hg(HBLK, BATCH);
    hist0_kernel<<<hg, 256>>>((const float4*)coeffs);
    hist1_kernel<<<hg, 256>>>((const float4*)coeffs);

    dim3 fg(FBLK, BATCH);
    final_kernel<<<fg, 256>>>((const float4*)coeffs, temp, (float4*)out);
}